// round 17
// baseline (speedup 1.0000x reference)
#include <cuda_runtime.h>
#include <cuda_fp16.h>
#include <cstdint>

// Problem: x [8,4096,512] f32, codebook [4096,512] f32
//   N = 32768 tokens, M = 4096 codes, K = 512
// Out (f32, concatenated): q_st [N*512], commitment_loss [N], cb_n [M*512]
//
// R17 = R16 with g_cand transposed to [group][token][2]:
//   GEMM epilogue key writes become 128B-contiguous (full 32B sectors)
//   instead of 16B-every-1KB (half-sector waste). Select reads the
//   transposed layout; unique bytes unchanged, L2 absorbs granularity.

#define NTOK   32768
#define MCODE  4096
#define KDIM   512
#define EPSN   1e-12f
#define TAU    1e-3f
#define NGRP   (MCODE / 64)                 // 64 groups per token

#define TILE        128
#define KC          64                      // fp16 per k-chunk (128 B rows)
#define NSTAGE      3
#define ATILE_BYTES (TILE * 128)            // 16384
#define STAGE_BYTES (2 * ATILE_BYTES)       // A + B
#define DYN_SMEM    (NSTAGE * STAGE_BYTES)  // 98304 -> 2 CTAs/SM
#define NITER       (KDIM / KC)             // 8

// ---------------- device scratch (no allocs allowed) ----------------
__device__ __half             g_xs[(size_t)NTOK * KDIM];    // fp16(x)      32 MB
__device__ __half             g_bs[(size_t)MCODE * KDIM];   // fp16(raw cb)  4 MB
__device__ float              g_cbn[(size_t)MCODE * KDIM];  // normalized cb 8 MB
__device__ float              g_invnb[MCODE];
__device__ float              g_invnx[NTOK];
__device__ unsigned long long g_cand[(size_t)NGRP * NTOK * 2];  // 32 MB, [g][n][2]

// ---------------- helpers ----------------
__device__ __forceinline__ uint32_t smem_u32(const void* p) {
    uint32_t a;
    asm("{ .reg .u64 t; cvta.to.shared.u64 t, %1; cvt.u32.u64 %0, t; }"
        : "=r"(a) : "l"(p));
    return a;
}
__device__ __forceinline__ void cp_async16(uint32_t s, const void* g) {
    asm volatile("cp.async.cg.shared.global [%0], [%1], 16;" :: "r"(s), "l"(g));
}
__device__ __forceinline__ void ldsm_x4(uint32_t* r, uint32_t addr) {
    asm volatile("ldmatrix.sync.aligned.m8n8.x4.shared.b16 {%0,%1,%2,%3}, [%4];"
                 : "=r"(r[0]), "=r"(r[1]), "=r"(r[2]), "=r"(r[3]) : "r"(addr));
}
__device__ __forceinline__ void mma16816(float* c, const uint32_t* a,
                                         const uint32_t* b) {
    asm volatile(
        "mma.sync.aligned.m16n8k16.row.col.f32.f16.f16.f32 "
        "{%0,%1,%2,%3}, {%4,%5,%6,%7}, {%8,%9}, {%0,%1,%2,%3};"
        : "+f"(c[0]), "+f"(c[1]), "+f"(c[2]), "+f"(c[3])
        : "r"(a[0]), "r"(a[1]), "r"(a[2]), "r"(a[3]), "r"(b[0]), "r"(b[1]));
}

// monotone float<->uint (order-preserving); key = (flipped score || ~idx)
__device__ __forceinline__ unsigned flip_f(unsigned fb) {
    return (fb & 0x80000000u) ? ~fb : (fb | 0x80000000u);
}
__device__ __forceinline__ unsigned unflip_f(unsigned u) {
    return (u & 0x80000000u) ? (u & 0x7FFFFFFFu) : ~u;
}
__device__ __forceinline__ unsigned long long make_key(unsigned fbits, int idx) {
    return (((unsigned long long)flip_f(fbits)) << 32) |
           (unsigned long long)(0xFFFFFFFFu - (unsigned)idx);
}
__device__ __forceinline__ float key_score(unsigned long long k) {
    return __uint_as_float(unflip_f((unsigned)(k >> 32)));
}
__device__ __forceinline__ int key_idx(unsigned long long k) {
    return (int)(0xFFFFFFFFu - (unsigned)(k & 0xFFFFFFFFull));
}

// ---------------- kernel 1: merged prep (cb rows then x rows) ----------------
// grid = MCODE + NTOK blocks of 128 threads.
__global__ void prep_kernel(const float* __restrict__ x,
                            const float* __restrict__ cb,
                            float* __restrict__ out_cb) {
    const int row = blockIdx.x;
    const int tid = threadIdx.x;
    __shared__ float ws[4];
    __shared__ float sinv;

    if (row < MCODE) {
        // ---- codebook row: norm + normalized copy + fp16 of raw ----
        const float4 v = *(const float4*)(cb + (size_t)row * KDIM + tid * 4);
        float s = v.x * v.x + v.y * v.y + v.z * v.z + v.w * v.w;
        #pragma unroll
        for (int off = 16; off > 0; off >>= 1) s += __shfl_down_sync(~0u, s, off);
        if ((tid & 31) == 0) ws[tid >> 5] = s;
        __syncthreads();
        if (tid == 0) {
            float inv = 1.0f / fmaxf(sqrtf(ws[0] + ws[1] + ws[2] + ws[3]), EPSN);
            sinv = inv;
            g_invnb[row] = inv;
        }
        __syncthreads();
        const float inv = sinv;
        float o[4] = {v.x * inv, v.y * inv, v.z * inv, v.w * inv};
        size_t fb = (size_t)row * KDIM + tid * 4;
        *(float4*)(g_cbn + fb) = *(float4*)o;
        if (out_cb) *(float4*)(out_cb + fb) = *(float4*)o;
        __half h[4] = {__float2half_rn(v.x), __float2half_rn(v.y),
                       __float2half_rn(v.z), __float2half_rn(v.w)};
        *(uint2*)(g_bs + fb) = *(uint2*)h;
    } else {
        // ---- x row: inv-norm + fp16 ----
        const int r = row - MCODE;
        const float4 v = *(const float4*)(x + (size_t)r * KDIM + tid * 4);
        float s = v.x * v.x + v.y * v.y + v.z * v.z + v.w * v.w;
        #pragma unroll
        for (int off = 16; off > 0; off >>= 1) s += __shfl_down_sync(~0u, s, off);
        if ((tid & 31) == 0) ws[tid >> 5] = s;
        __syncthreads();
        if (tid == 0)
            g_invnx[r] = 1.0f / fmaxf(sqrtf(ws[0] + ws[1] + ws[2] + ws[3]), EPSN);
        __half h[4] = {__float2half_rn(v.x), __float2half_rn(v.y),
                       __float2half_rn(v.z), __float2half_rn(v.w)};
        *(uint2*)(g_xs + (size_t)r * KDIM + tid * 4) = *(uint2*)h;
    }
}

// ---------------- kernel 2 (pass 1): fp16 HMMA GEMM -> top-2 keys/group ----------------
// grid (MCODE/TILE=32 inner, NTOK/TILE=256); 256 threads; warp tile 32x64.
extern "C" __global__ void __launch_bounds__(256, 2)
vq_hmma_kernel() {
    extern __shared__ char smem[];
    __shared__ float s_invb[TILE];
    __shared__ float s_invx[TILE];

    const int tid = threadIdx.x;
    const int wid = tid >> 5;
    const int lid = tid & 31;
    const int mBase = blockIdx.x * TILE;   // codes
    const int nBase = blockIdx.y * TILE;   // tokens

    if (tid < TILE) {
        s_invb[tid] = g_invnb[mBase + tid];
        s_invx[tid] = g_invnx[nBase + tid];
    }

    const uint32_t sbase = smem_u32(smem);

    // ---- cp.async coordinates: thread -> (row, 64B-half), 4x16B each op ----
    const int ldrow = tid >> 1;
    const int ldhalf = tid & 1;
    const __half* aSrc = g_xs + (size_t)(nBase + ldrow) * KDIM + ldhalf * 32;
    const __half* bSrc = g_bs + (size_t)(mBase + ldrow) * KDIM + ldhalf * 32;
    uint32_t aDst[4], bDst[4];
    {
        const uint32_t xr = (ldrow & 7) << 4;   // SW128 xor
        #pragma unroll
        for (int q = 0; q < 4; q++) {
            uint32_t cbyte = ldhalf * 64 + q * 16;
            uint32_t off = ldrow * 128 + (cbyte ^ xr);
            aDst[q] = off;
            bDst[q] = ATILE_BYTES + off;
        }
    }

    // ---- ldmatrix lane addressing ----
    const int wRow = (wid & 3) * 32;   // token rows of this warp
    const int wCol = (wid >> 2) * 64;  // code cols of this warp
    uint32_t aRowOff[2], aXor[2];
    #pragma unroll
    for (int mt = 0; mt < 2; mt++) {
        int r = wRow + mt * 16 + (lid & 7) + ((lid >> 3) & 1) * 8;
        aRowOff[mt] = r * 128;
        aXor[mt] = (r & 7) << 4;
    }
    const uint32_t aCb = ((lid >> 4) & 1) * 16;
    uint32_t bRowOff[4], bXor[4];
    #pragma unroll
    for (int np = 0; np < 4; np++) {
        int r = wCol + np * 16 + (lid & 7) + ((lid >> 4) & 1) * 8;
        bRowOff[np] = ATILE_BYTES + r * 128;
        bXor[np] = (r & 7) << 4;
    }
    const uint32_t bCb = ((lid >> 3) & 1) * 16;

    float acc[2][8][4];
    #pragma unroll
    for (int mt = 0; mt < 2; mt++)
        #pragma unroll
        for (int nt = 0; nt < 8; nt++)
            #pragma unroll
            for (int j = 0; j < 4; j++) acc[mt][nt][j] = 0.0f;

#define ISSUE(stage, bufi) do {                                           \
        uint32_t sb_ = sbase + (bufi) * STAGE_BYTES;                      \
        const __half* a_ = aSrc + (stage) * KC;                           \
        const __half* b_ = bSrc + (stage) * KC;                           \
        _Pragma("unroll")                                                 \
        for (int q = 0; q < 4; q++) cp_async16(sb_ + aDst[q], a_ + q * 8);\
        _Pragma("unroll")                                                 \
        for (int q = 0; q < 4; q++) cp_async16(sb_ + bDst[q], b_ + q * 8);\
    } while (0)

    // prologue: stages 0,1 in flight (buffers 0,1; buffer 2 free)
    ISSUE(0, 0);
    asm volatile("cp.async.commit_group;" ::: "memory");
    ISSUE(1, 1);
    asm volatile("cp.async.commit_group;" ::: "memory");

    int buf = 0;
    int ibuf = 2;
    for (int i = 0; i < NITER; i++) {
        asm volatile("cp.async.wait_group 1;" ::: "memory");
        __syncthreads();

        if (i + 2 < NITER) ISSUE(i + 2, ibuf);
        asm volatile("cp.async.commit_group;" ::: "memory");

        const uint32_t sb = sbase + buf * STAGE_BYTES;
        #pragma unroll
        for (int ks = 0; ks < 4; ks++) {
            uint32_t a[2][4];
            #pragma unroll
            for (int mt = 0; mt < 2; mt++)
                ldsm_x4(a[mt], sb + aRowOff[mt] + (((uint32_t)ks * 32 + aCb) ^ aXor[mt]));
            uint32_t b[4][4];
            #pragma unroll
            for (int np = 0; np < 4; np++)
                ldsm_x4(b[np], sb + bRowOff[np] + (((uint32_t)ks * 32 + bCb) ^ bXor[np]));
            #pragma unroll
            for (int mt = 0; mt < 2; mt++)
                #pragma unroll
                for (int nt = 0; nt < 8; nt++)
                    mma16816(acc[mt][nt], a[mt], &b[nt >> 1][(nt & 1) * 2]);
        }

        buf = (buf == NSTAGE - 1) ? 0 : buf + 1;
        ibuf = (ibuf == NSTAGE - 1) ? 0 : ibuf + 1;
    }

    // ---- epilogue: per-row top-2 COSINE keys over this warp's 64-code group ----
    // [group][token][2] layout: the 8 writing lanes cover 8 consecutive
    // tokens -> 128B contiguous stores (full sectors).
    const int g = blockIdx.x * 2 + (wid >> 2);   // 64-code group index
    #pragma unroll
    for (int mt = 0; mt < 2; mt++) {
        #pragma unroll
        for (int sub = 0; sub < 2; sub++) {
            const int rowLocal = wRow + mt * 16 + sub * 8 + (lid >> 2);
            const float invx = s_invx[rowLocal];
            unsigned long long t1 = 0ull, t2 = 0ull;
            #pragma unroll
            for (int nt = 0; nt < 8; nt++) {
                #pragma unroll
                for (int j = 0; j < 2; j++) {
                    const int cl = wCol + nt * 8 + 2 * (lid & 3) + j;
                    float f = acc[mt][nt][sub * 2 + j] * s_invb[cl] * invx;
                    unsigned long long k = make_key(__float_as_uint(f), mBase + cl);
                    if (k > t1) { t2 = t1; t1 = k; }
                    else if (k > t2) { t2 = k; }
                }
            }
            // merge top-2 across the 4 lanes of this row quad (xor 1, 2)
            #pragma unroll
            for (int off = 1; off <= 2; off <<= 1) {
                unsigned long long o1 = __shfl_xor_sync(~0u, t1, off);
                unsigned long long o2 = __shfl_xor_sync(~0u, t2, off);
                unsigned long long n1 = (t1 > o1) ? t1 : o1;
                unsigned long long lo = (t1 > o1) ? o1 : t1;
                unsigned long long n2 = (t2 > o2) ? t2 : o2;
                t1 = n1;
                t2 = (lo > n2) ? lo : n2;
            }
            if ((lid & 3) == 0) {
                size_t base = ((size_t)g * NTOK + (nBase + rowLocal)) * 2;
                g_cand[base]     = t1;
                g_cand[base + 1] = t2;
            }
        }
    }
}

// ---------------- kernel 3 (pass 2): max + fast path / exact rescore ----------------
// one block of 128 threads per token; reads 128 keys (1 KB, [g][n][2] layout)
extern "C" __global__ void __launch_bounds__(128)
select_kernel(const float* __restrict__ x,
              float* __restrict__ q_out, float* __restrict__ loss_out) {
    const int n = blockIdx.x;
    const int tid = threadIdx.x;
    const int lid = tid & 31;
    const int wid = tid >> 5;

    __shared__ float s_x[KDIM];
    __shared__ unsigned long long s_wmax[4];
    __shared__ int s_cand[64];
    __shared__ int s_cnt;
    __shared__ unsigned long long s_bestk;

    if (tid == 0) { s_cnt = 0; s_bestk = 0ull; }

    // thread tid: group tid>>1, slot tid&1 ([g][n][2] layout)
    const unsigned long long k =
        g_cand[((size_t)(tid >> 1) * NTOK + n) * 2 + (tid & 1)];

    // block max of keys
    unsigned long long mk = k;
    #pragma unroll
    for (int off = 16; off > 0; off >>= 1) {
        unsigned long long o = __shfl_xor_sync(~0u, mk, off);
        if (o > mk) mk = o;
    }
    if (lid == 0) s_wmax[wid] = mk;
    __syncthreads();
    unsigned long long bm = s_wmax[0];
    #pragma unroll
    for (int w = 1; w < 4; w++) if (s_wmax[w] > bm) bm = s_wmax[w];
    const float thr = key_score(bm) - TAU;

    const int pred = (key_score(k) >= thr) ? 1 : 0;
    const int cnt = __syncthreads_count(pred);

    unsigned idx;
    if (cnt == 1) {
        // ---- fast path (~93%): unique candidate; filter cosine decides ----
        idx = (unsigned)key_idx(bm);
        if (tid == 0 && loss_out)
            loss_out[n] = 1.0f - key_score(bm);   // key IS cosine
    } else {
        // ---- slow path: exact fp32 rescore of all within-TAU candidates ----
        if (pred) {
            int pos = atomicAdd(&s_cnt, 1);
            if (pos < 64) s_cand[pos] = key_idx(k);
        }
        // x row -> smem (only needed here)
        *(float4*)(s_x + tid * 4) = *(const float4*)(x + (size_t)n * KDIM + tid * 4);
        __syncthreads();
        const int c_n = min(s_cnt, 64);
        for (int c = wid; c < c_n; c += 4) {
            const int m = s_cand[c];
            const float* cbrow = g_cbn + (size_t)m * KDIM;
            float sum = 0.0f;
            #pragma unroll
            for (int e = 0; e < KDIM / 32; e++) {
                int kk = e * 32 + lid;
                sum = fmaf(s_x[kk], cbrow[kk], sum);
            }
            #pragma unroll
            for (int off = 16; off > 0; off >>= 1)
                sum += __shfl_xor_sync(~0u, sum, off);
            if (lid == 0)
                atomicMax(&s_bestk, make_key(__float_as_uint(sum), m));
        }
        __syncthreads();
        const unsigned long long pk = s_bestk;
        idx = 0xFFFFFFFFu - (unsigned)(pk & 0xFFFFFFFFull);
        if (tid == 0 && loss_out)
            loss_out[n] = 1.0f - key_score(pk) * g_invnx[n];  // dot -> cosine
    }

    // output: q_st row = normalized codebook row of the winner
    *(float4*)(q_out + (size_t)n * KDIM + tid * 4) =
        *(const float4*)(g_cbn + (size_t)idx * KDIM + tid * 4);
}

// ---------------- host launch ----------------
extern "C" void kernel_launch(void* const* d_in, const int* in_sizes, int n_in,
                              void* d_out, int out_size) {
    const float* x  = (const float*)d_in[0];
    const float* cb = (const float*)d_in[1];
    const int N = in_sizes[0] / KDIM;   // 32768
    const int M = in_sizes[1] / KDIM;   // 4096

    float* out = (float*)d_out;
    float* q_out = out;
    float* loss_out = nullptr;
    float* cb_out = nullptr;
    long long need_full = (long long)N * KDIM + N + (long long)M * KDIM;
    if ((long long)out_size >= need_full) {
        loss_out = out + (size_t)N * KDIM;
        cb_out = loss_out + N;
    } else if ((long long)out_size >= (long long)N * KDIM + N) {
        loss_out = out + (size_t)N * KDIM;
    }

    cudaFuncSetAttribute(vq_hmma_kernel,
                         cudaFuncAttributeMaxDynamicSharedMemorySize, DYN_SMEM);

    prep_kernel<<<M + N, 128>>>(x, cb, cb_out);

    dim3 grid(M / TILE, N / TILE);   // codes inner -> B (4 MB fp16) hot in L2
    vq_hmma_kernel<<<grid, 256, DYN_SMEM>>>();

    select_kernel<<<N, 128>>>(x, q_out, loss_out);
}